// round 1
// baseline (speedup 1.0000x reference)
#include <cuda_runtime.h>
#include <math.h>

#define LAMBDA 1.5f
#define B_SZ 32
#define N_SZ 2048
#define HID 256
#define WARPS_PER_BLOCK 8

__device__ float g_scale[B_SZ];

// ---------------------------------------------------------------------------
// Kernel 1: per-batch scale = -(L^2) * (1 - mean_n(x_r^2 + x_i^2))
// ---------------------------------------------------------------------------
__global__ void scale_kernel(const float* __restrict__ xr,
                             const float* __restrict__ xi) {
    const int b = blockIdx.x;
    const int tid = threadIdx.x;
    const float* xrb = xr + (size_t)b * N_SZ;
    const float* xib = xi + (size_t)b * N_SZ;

    float s = 0.f;
    for (int k = tid; k < N_SZ; k += blockDim.x) {
        float a = xrb[k];
        float c = xib[k];
        s = fmaf(a, a, s);
        s = fmaf(c, c, s);
    }
    // warp reduce
    for (int off = 16; off > 0; off >>= 1)
        s += __shfl_xor_sync(0xFFFFFFFFu, s, off);

    __shared__ float warp_sums[8];
    const int wid = tid >> 5;
    const int lid = tid & 31;
    if (lid == 0) warp_sums[wid] = s;
    __syncthreads();
    if (tid == 0) {
        float tot = 0.f;
        const int nw = blockDim.x >> 5;
        for (int w = 0; w < nw; w++) tot += warp_sums[w];
        float mean = tot / (float)N_SZ;
        g_scale[b] = -(LAMBDA * LAMBDA) * (1.0f - mean);
    }
}

// ---------------------------------------------------------------------------
// Kernel 2: fused complex matvec + epilogue (Dense(1), scale*x_prev, MLP, q)
// grid: (N/WARPS_PER_BLOCK, B), block: 256 threads (8 warps, 1 row each)
// ---------------------------------------------------------------------------
__global__ __launch_bounds__(256) void matvec_kernel(
    const float* __restrict__ Yr, const float* __restrict__ Yi,
    const float* __restrict__ xr, const float* __restrict__ xi,
    const float* __restrict__ xpr, const float* __restrict__ xpi,
    const float* __restrict__ d3w, const float* __restrict__ d3b,
    const float* __restrict__ w1, const float* __restrict__ b1,
    const float* __restrict__ w2, const float* __restrict__ b2,
    float* __restrict__ out) {

    __shared__ float sxr[N_SZ];
    __shared__ float sxi[N_SZ];
    __shared__ float sw1[HID];
    __shared__ float sb1[HID];
    __shared__ float sw2[HID];

    const int tid = threadIdx.x;
    const int b = blockIdx.y;

    // Stage x vectors for this batch into shared (float4 loads)
    {
        const float4* xr4 = (const float4*)(xr + (size_t)b * N_SZ);
        const float4* xi4 = (const float4*)(xi + (size_t)b * N_SZ);
        float4* sxr4 = (float4*)sxr;
        float4* sxi4 = (float4*)sxi;
        for (int k = tid; k < N_SZ / 4; k += 256) {
            sxr4[k] = xr4[k];
            sxi4[k] = xi4[k];
        }
        // MLP weights
        if (tid < HID) {
            sw1[tid] = w1[tid];
            sb1[tid] = b1[tid];
            sw2[tid] = w2[tid];
        }
    }
    __syncthreads();

    const int wid = tid >> 5;   // warp -> row within group
    const int lid = tid & 31;
    const int n = blockIdx.x * WARPS_PER_BLOCK + wid;

    const size_t row_base = (((size_t)b * N_SZ) + n) * N_SZ;
    const float4* yr4 = (const float4*)(Yr + row_base);
    const float4* yi4 = (const float4*)(Yi + row_base);
    const float4* sxr4 = (const float4*)sxr;
    const float4* sxi4 = (const float4*)sxi;

    float rr = 0.f, ii = 0.f, ri = 0.f, ir = 0.f;

    #pragma unroll 4
    for (int k = lid; k < N_SZ / 4; k += 32) {
        float4 a = yr4[k];
        float4 c = yi4[k];
        float4 u = sxr4[k];
        float4 v = sxi4[k];
        rr = fmaf(a.x, u.x, rr); rr = fmaf(a.y, u.y, rr);
        rr = fmaf(a.z, u.z, rr); rr = fmaf(a.w, u.w, rr);
        ii = fmaf(c.x, v.x, ii); ii = fmaf(c.y, v.y, ii);
        ii = fmaf(c.z, v.z, ii); ii = fmaf(c.w, v.w, ii);
        ri = fmaf(a.x, v.x, ri); ri = fmaf(a.y, v.y, ri);
        ri = fmaf(a.z, v.z, ri); ri = fmaf(a.w, v.w, ri);
        ir = fmaf(c.x, u.x, ir); ir = fmaf(c.y, u.y, ir);
        ir = fmaf(c.z, u.z, ir); ir = fmaf(c.w, u.w, ir);
    }

    // butterfly reduce all four accumulators -> every lane has full sums
    for (int off = 16; off > 0; off >>= 1) {
        rr += __shfl_xor_sync(0xFFFFFFFFu, rr, off);
        ii += __shfl_xor_sync(0xFFFFFFFFu, ii, off);
        ri += __shfl_xor_sync(0xFFFFFFFFu, ri, off);
        ir += __shfl_xor_sync(0xFFFFFFFFu, ir, off);
    }

    // Epilogue (all lanes compute identically up to the MLP partial)
    const float dw = d3w[0];
    const float db = d3b[0];
    const float sc = g_scale[b];
    const size_t idx = (size_t)b * N_SZ + n;

    float x1r = fmaf(LAMBDA * (rr - ii), dw, db);
    float x1i = fmaf(LAMBDA * (ri + ir), dw, db);
    x1r = fmaf(sc, xpr[idx], x1r);
    x1i = fmaf(sc, xpi[idx], x1i);

    const float xabs = sqrtf(x1r * x1r + x1i * x1i);

    // MLP: 256 hidden units, 8 per lane
    float partial = 0.f;
    #pragma unroll
    for (int j = lid; j < HID; j += 32) {
        float h = fmaxf(fmaf(xabs, sw1[j], sb1[j]), 0.f);
        partial = fmaf(h, sw2[j], partial);
    }
    for (int off = 16; off > 0; off >>= 1)
        partial += __shfl_xor_sync(0xFFFFFFFFu, partial, off);

    if (lid == 0) {
        float g = tanhf(partial + b2[0]);
        float q = g / fmaxf(xabs, 1e-12f);
        out[idx] = x1r * q;                                  // real part
        out[(size_t)B_SZ * N_SZ + idx] = x1i * q;            // imag part
    }
}

extern "C" void kernel_launch(void* const* d_in, const int* in_sizes, int n_in,
                              void* d_out, int out_size) {
    const float* Yr  = (const float*)d_in[0];
    const float* Yi  = (const float*)d_in[1];
    const float* xr  = (const float*)d_in[2];
    const float* xi  = (const float*)d_in[3];
    const float* xpr = (const float*)d_in[4];
    const float* xpi = (const float*)d_in[5];
    const float* d3w = (const float*)d_in[6];
    const float* d3b = (const float*)d_in[7];
    const float* w1  = (const float*)d_in[8];
    const float* b1  = (const float*)d_in[9];
    const float* w2  = (const float*)d_in[10];
    const float* b2  = (const float*)d_in[11];
    float* out = (float*)d_out;

    scale_kernel<<<B_SZ, 256>>>(xr, xi);

    dim3 grid(N_SZ / WARPS_PER_BLOCK, B_SZ);
    matvec_kernel<<<grid, 256>>>(Yr, Yi, xr, xi, xpr, xpi,
                                 d3w, d3b, w1, b1, w2, b2, out);
}